// round 1
// baseline (speedup 1.0000x reference)
#include <cuda_runtime.h>
#include <math.h>
#include <stdint.h>

#define BB 4
#define CC 256
#define LL 2304        // 48*48
#define NHH 8
#define DKK 64
#define DD 512         // NHH*DKK
#define BN_EPS 1e-5f
#define NEG_SLOPE 0.01f

// ---------------- scratch (allocation-free: __device__ globals) ----------------
__device__ float g_q[(size_t)BB * DD * LL];
__device__ float g_k[(size_t)BB * DD * LL];
__device__ float g_v[(size_t)BB * DD * LL];
__device__ float g_attn[(size_t)BB * DD * LL];
__device__ float g_proj[(size_t)BB * CC * LL];
__device__ float g_mean[CC];
__device__ float g_rstd[CC];

// ---------------------------------------------------------------------------
// Generic W*X GEMM:  Out[b][m][n] = sum_k W[m*K+k] * In[b][k][n]
// Tiles: 64x64 output, 16 k-step. 256 threads, each computes 4x4.
// Requires M%64==0, N%64==0, K%16==0 (all true here).
// ---------------------------------------------------------------------------
__global__ void gemm_wx(const float* __restrict__ W, const float* __restrict__ In,
                        float* __restrict__ Out, int M, int K, int N) {
    __shared__ float Ws[16][64];   // [k][m]
    __shared__ float Is[16][64];   // [k][n]

    const int b  = blockIdx.z;
    const float* in  = In  + (size_t)b * K * N;
    float*       out = Out + (size_t)b * M * N;
    const int m0 = blockIdx.y * 64;
    const int n0 = blockIdx.x * 64;
    const int tid = threadIdx.x;
    const int ty = tid >> 4;       // 0..15
    const int tx = tid & 15;       // 0..15

    float acc[4][4] = {};

    for (int k0 = 0; k0 < K; k0 += 16) {
        // Is: 16 rows x 16 float4; one float4 per thread, coalesced
        {
            int r = tid >> 4, v = tid & 15;
            float4 t = *(const float4*)(in + (size_t)(k0 + r) * N + n0 + v * 4);
            *(float4*)&Is[r][v * 4] = t;
        }
        // Ws: read W[m][k] as float4 along k, store transposed [k][m]
        {
            int mm = tid >> 2, kg = tid & 3;
            float4 t = *(const float4*)(W + (size_t)(m0 + mm) * K + k0 + kg * 4);
            Ws[kg * 4 + 0][mm] = t.x;
            Ws[kg * 4 + 1][mm] = t.y;
            Ws[kg * 4 + 2][mm] = t.z;
            Ws[kg * 4 + 3][mm] = t.w;
        }
        __syncthreads();

        #pragma unroll
        for (int kk = 0; kk < 16; kk++) {
            float wv[4], iv[4];
            #pragma unroll
            for (int i = 0; i < 4; i++) wv[i] = Ws[kk][ty * 4 + i];
            #pragma unroll
            for (int j = 0; j < 4; j++) iv[j] = Is[kk][tx * 4 + j];
            #pragma unroll
            for (int i = 0; i < 4; i++)
                #pragma unroll
                for (int j = 0; j < 4; j++)
                    acc[i][j] += wv[i] * iv[j];
        }
        __syncthreads();
    }

    #pragma unroll
    for (int i = 0; i < 4; i++)
        #pragma unroll
        for (int j = 0; j < 4; j++)
            out[(size_t)(m0 + ty * 4 + i) * N + n0 + tx * 4 + j] = acc[i][j];
}

// ---------------------------------------------------------------------------
// Fused flash-style attention. Q/K/V in [bh][d][l] layout (d-major).
// Block = 64 queries of one (b,h). Streams 64-key tiles, online softmax.
// Writes g_attn[bh*DK + d][l=q].
// ---------------------------------------------------------------------------
struct AttnSmem {
    float Qs[DKK][64];   // [d][q], pre-scaled by 1/8
    float Ks[DKK][64];   // [d][k]
    float Vs[64][DKK];   // [k][d]  (transposed for conflict-free PV)
    float Ps[64][68];    // [q][k], padded stride
    float m[64];
    float l[64];
    float scale[64];
};

__global__ void attn_kernel() {
    extern __shared__ char smem_raw[];
    AttnSmem* S = (AttnSmem*)smem_raw;

    const int bh = blockIdx.y;             // b*NH + h
    const int q0 = blockIdx.x * 64;
    const float* Qp = g_q + (size_t)bh * DKK * LL;
    const float* Kp = g_k + (size_t)bh * DKK * LL;
    const float* Vp = g_v + (size_t)bh * DKK * LL;

    const int tid = threadIdx.x;
    const int ty = tid >> 4, tx = tid & 15;

    // Load Q tile [64 d][64 q], scaled by 1/sqrt(DK)=0.125
    #pragma unroll
    for (int i = 0; i < 4; i++) {
        int d = i * 16 + (tid >> 4);
        int v = tid & 15;
        float4 t = *(const float4*)(Qp + (size_t)d * LL + q0 + v * 4);
        t.x *= 0.125f; t.y *= 0.125f; t.z *= 0.125f; t.w *= 0.125f;
        *(float4*)&S->Qs[d][v * 4] = t;
    }
    if (tid < 64) { S->m[tid] = -1e30f; S->l[tid] = 0.0f; }

    float o[4][4] = {};   // [qi][di]

    for (int k0 = 0; k0 < LL; k0 += 64) {
        __syncthreads();   // previous iteration fully consumed Ks/Vs/Ps

        // Load K tile [d][k] and V tile transposed [k][d]
        #pragma unroll
        for (int i = 0; i < 4; i++) {
            int d = i * 16 + (tid >> 4);
            int v = tid & 15;
            *(float4*)&S->Ks[d][v * 4] =
                *(const float4*)(Kp + (size_t)d * LL + k0 + v * 4);
            float4 t = *(const float4*)(Vp + (size_t)d * LL + k0 + v * 4);
            S->Vs[v * 4 + 0][d] = t.x;
            S->Vs[v * 4 + 1][d] = t.y;
            S->Vs[v * 4 + 2][d] = t.z;
            S->Vs[v * 4 + 3][d] = t.w;
        }
        __syncthreads();

        // Logits: s[qi][ki] = sum_d Qs[d][q] * Ks[d][k]
        float s[4][4] = {};
        #pragma unroll
        for (int d = 0; d < DKK; d++) {
            float qv[4], kv[4];
            #pragma unroll
            for (int i = 0; i < 4; i++) qv[i] = S->Qs[d][ty * 4 + i];
            #pragma unroll
            for (int j = 0; j < 4; j++) kv[j] = S->Ks[d][tx * 4 + j];
            #pragma unroll
            for (int i = 0; i < 4; i++)
                #pragma unroll
                for (int j = 0; j < 4; j++)
                    s[i][j] += qv[i] * kv[j];
        }
        #pragma unroll
        for (int i = 0; i < 4; i++)
            #pragma unroll
            for (int j = 0; j < 4; j++)
                S->Ps[ty * 4 + i][tx * 4 + j] = s[i][j];
        __syncthreads();

        // Row max + rescale factor (threads 0..63, one row each)
        if (tid < 64) {
            float mo = S->m[tid];
            float mn = mo;
            #pragma unroll 8
            for (int k = 0; k < 64; k++) mn = fmaxf(mn, S->Ps[tid][k]);
            float sc = __expf(mo - mn);
            S->scale[tid] = sc;
            S->m[tid] = mn;
            S->l[tid] *= sc;
        }
        __syncthreads();

        // Exponentiate in place
        #pragma unroll
        for (int i = 0; i < 4; i++) {
            float mm = S->m[ty * 4 + i];
            #pragma unroll
            for (int j = 0; j < 4; j++)
                S->Ps[ty * 4 + i][tx * 4 + j] =
                    __expf(S->Ps[ty * 4 + i][tx * 4 + j] - mm);
        }
        __syncthreads();

        // Row sums (readers only; concurrent with PV reads below is fine,
        // but keep ordering simple: do sums first inside the same phase)
        if (tid < 64) {
            float sum = 0.0f;
            #pragma unroll 8
            for (int k = 0; k < 64; k++) sum += S->Ps[tid][k];
            S->l[tid] += sum;
        }

        // Rescale accumulators, then PV: o[qi][di] += P[q][k] * V[k][d]
        #pragma unroll
        for (int i = 0; i < 4; i++) {
            float sc = S->scale[ty * 4 + i];
            #pragma unroll
            for (int j = 0; j < 4; j++) o[i][j] *= sc;
        }
        #pragma unroll
        for (int k = 0; k < 64; k++) {
            float pv[4], vv[4];
            #pragma unroll
            for (int i = 0; i < 4; i++) pv[i] = S->Ps[ty * 4 + i][k];
            #pragma unroll
            for (int j = 0; j < 4; j++) vv[j] = S->Vs[k][tx * 4 + j];
            #pragma unroll
            for (int i = 0; i < 4; i++)
                #pragma unroll
                for (int j = 0; j < 4; j++)
                    o[i][j] += pv[i] * vv[j];
        }
    }
    __syncthreads();

    // Normalize and write out in [d][l] layout for the Wo GEMM
    float* Op = g_attn + (size_t)bh * DKK * LL;
    #pragma unroll
    for (int i = 0; i < 4; i++) {
        float inv = 1.0f / S->l[ty * 4 + i];
        #pragma unroll
        for (int j = 0; j < 4; j++)
            Op[(size_t)(tx * 4 + j) * LL + q0 + ty * 4 + i] = o[i][j] * inv;
    }
}

// ---------------------------------------------------------------------------
// BatchNorm statistics: one block per channel, reduce over (b, l)
// ---------------------------------------------------------------------------
__global__ void bn_stats() {
    const int c = blockIdx.x;
    float sum = 0.0f, sumsq = 0.0f;
    for (int b = 0; b < BB; b++) {
        const float* p = g_proj + ((size_t)b * CC + c) * LL;
        for (int i = threadIdx.x; i < LL; i += blockDim.x) {
            float v = p[i];
            sum += v;
            sumsq += v * v;
        }
    }
    __shared__ float ss[256], sq[256];
    ss[threadIdx.x] = sum;
    sq[threadIdx.x] = sumsq;
    __syncthreads();
    for (int off = 128; off > 0; off >>= 1) {
        if (threadIdx.x < off) {
            ss[threadIdx.x] += ss[threadIdx.x + off];
            sq[threadIdx.x] += sq[threadIdx.x + off];
        }
        __syncthreads();
    }
    if (threadIdx.x == 0) {
        const float inv_n = 1.0f / (float)(BB * LL);
        float mean = ss[0] * inv_n;
        float var  = sq[0] * inv_n - mean * mean;
        g_mean[c] = mean;
        g_rstd[c] = rsqrtf(var + BN_EPS);
    }
}

// ---------------------------------------------------------------------------
// BN apply + gamma-scale + residual + LeakyReLU (float4 vectorized)
// ---------------------------------------------------------------------------
__global__ void bn_apply(const float* __restrict__ x,
                         const float* __restrict__ bn_w,
                         const float* __restrict__ bn_b,
                         const float* __restrict__ gamma,
                         float* __restrict__ out) {
    const size_t i4 = (size_t)blockIdx.x * blockDim.x + threadIdx.x;
    const size_t n4 = (size_t)BB * CC * LL / 4;
    if (i4 >= n4) return;
    const int c = (int)((i4 / (LL / 4)) % CC);
    const float mean = g_mean[c];
    const float rstd = g_rstd[c];
    const float w = bn_w[c] * rstd;
    const float bcon = bn_b[c] - mean * w;
    const float g = gamma[0];

    float4 v = ((const float4*)g_proj)[i4];
    float4 xr = ((const float4*)x)[i4];
    float4 y;
    y.x = g * (v.x * w + bcon) + xr.x;
    y.y = g * (v.y * w + bcon) + xr.y;
    y.z = g * (v.z * w + bcon) + xr.z;
    y.w = g * (v.w * w + bcon) + xr.w;
    y.x = y.x >= 0.0f ? y.x : NEG_SLOPE * y.x;
    y.y = y.y >= 0.0f ? y.y : NEG_SLOPE * y.y;
    y.z = y.z >= 0.0f ? y.z : NEG_SLOPE * y.z;
    y.w = y.w >= 0.0f ? y.w : NEG_SLOPE * y.w;
    ((float4*)out)[i4] = y;
}

// ---------------------------------------------------------------------------
extern "C" void kernel_launch(void* const* d_in, const int* in_sizes, int n_in,
                              void* d_out, int out_size) {
    const float* x     = (const float*)d_in[0];
    const float* Wq    = (const float*)d_in[1];
    const float* Wk    = (const float*)d_in[2];
    const float* Wv    = (const float*)d_in[3];
    const float* Wo    = (const float*)d_in[4];
    const float* bn_w  = (const float*)d_in[5];
    const float* bn_b  = (const float*)d_in[6];
    const float* gamma = (const float*)d_in[7];
    float* out = (float*)d_out;

    float *gq, *gk, *gv, *gattn, *gproj;
    cudaGetSymbolAddress((void**)&gq,    g_q);
    cudaGetSymbolAddress((void**)&gk,    g_k);
    cudaGetSymbolAddress((void**)&gv,    g_v);
    cudaGetSymbolAddress((void**)&gattn, g_attn);
    cudaGetSymbolAddress((void**)&gproj, g_proj);

    static bool attr_set = false;
    if (!attr_set) {
        cudaFuncSetAttribute(attn_kernel,
                             cudaFuncAttributeMaxDynamicSharedMemorySize,
                             (int)sizeof(AttnSmem));
        attr_set = true;
    }

    // Q/K/V projections: [512x256] x [256x2304] per batch
    dim3 gproj_grid(LL / 64, DD / 64, BB);
    gemm_wx<<<gproj_grid, 256>>>(Wq, x, gq, DD, CC, LL);
    gemm_wx<<<gproj_grid, 256>>>(Wk, x, gk, DD, CC, LL);
    gemm_wx<<<gproj_grid, 256>>>(Wv, x, gv, DD, CC, LL);

    // Fused attention: 36 q-tiles x 32 (b,h)
    attn_kernel<<<dim3(LL / 64, BB * NHH), 256, sizeof(AttnSmem)>>>();

    // Output projection: [256x512] x [512x2304] per batch
    gemm_wx<<<dim3(LL / 64, CC / 64, BB), 256>>>(Wo, gattn, gproj, CC, DD, LL);

    // BatchNorm stats + fused epilogue
    bn_stats<<<CC, 256>>>();
    const int n4 = BB * CC * LL / 4;
    bn_apply<<<(n4 + 255) / 256, 256>>>(x, bn_w, bn_b, gamma, out);
}